// round 11
// baseline (speedup 1.0000x reference)
#include <cuda_runtime.h>
#include <cuda_bf16.h>
#include <math.h>

#define MAX_T 11
#define HIDDEN 768
#define MAX_S 64
#define MAX_ROWS 64

// Scratch (no device allocation allowed).
__device__ float g_w[MAX_ROWS];

// ---------------------------------------------------------------------------
// K1: single-stage weights producer. One block per slice; warp d computes the
// dot product for valid turn d (row off+d), block does the softmax locally.
// No inter-block communication at all -> latency = one DRAM round trip.
// ---------------------------------------------------------------------------
__global__ void __launch_bounds__(32 * MAX_T)
k_weights(const float* __restrict__ hist,
          const float* __restrict__ W,
          const float* __restrict__ b,
          const int*   __restrict__ slice_mask,
          float* __restrict__ out_probs,
          int rows, int S)
{
    cudaTriggerProgrammaticLaunchCompletion();

    __shared__ int   s_mask[MAX_S];
    __shared__ float s_e[MAX_T];

    int tid  = threadIdx.x;
    int warp = tid >> 5, lane = tid & 31;
    int s = blockIdx.x;

    if (tid < S) s_mask[tid] = slice_mask[tid];
    __syncthreads();

    int off = 0;
    #pragma unroll 4
    for (int k = 0; k < s; k++) off += s_mask[k];
    int n = s_mask[s];
    if (n > MAX_T) n = MAX_T;

    // warp d -> dot(hist[off+d], W) for valid turn index d (= turn pad+d)
    if (warp < n) {
        int idx = off + warp;
        if (idx < 0) idx = 0;
        if (idx >= rows) idx = rows - 1;
        const float4* h4 = (const float4*)(hist + (size_t)idx * HIDDEN);
        const float4* w4 = (const float4*)W;
        float acc = 0.f;
        #pragma unroll
        for (int c = 0; c < HIDDEN / 4 / 32; c++) {   // 6 float4 per lane
            float4 hv = h4[lane + c * 32];
            float4 wv = w4[lane + c * 32];
            acc += hv.x * wv.x + hv.y * wv.y + hv.z * wv.z + hv.w * wv.w;
        }
        #pragma unroll
        for (int o = 16; o; o >>= 1) acc += __shfl_xor_sync(0xffffffffu, acc, o);
        if (lane == 0) s_e[warp] = __expf(acc + b[0]);
    }
    __syncthreads();

    // softmax over the n valid turns; emit probs (pad zeros) and g_w
    float sum = 0.f;
    #pragma unroll 4
    for (int k = 0; k < n; k++) sum += s_e[k];
    float inv = 1.f / sum;

    int pad = MAX_T - n;
    if (tid < MAX_T)
        out_probs[s * MAX_T + tid] = (tid < pad) ? 0.f : s_e[tid - pad] * inv;
    if (tid < n)
        g_w[off + tid] = s_e[tid] * inv;
}

// ---------------------------------------------------------------------------
// K2: weighted segment sum (PDL secondary). 2 output float4 per thread
// (8 independent preloads in flight before the grid-dependency sync).
// ---------------------------------------------------------------------------
__global__ void __launch_bounds__(256)
k_segsum(const float4* __restrict__ bert,
         float4* __restrict__ out_bert,
         const float4* __restrict__ mtl,
         float4* __restrict__ out_mtl,
         const int* __restrict__ slice_mask,
         int half_bert, int vec_bert, int vec_mtl, int bert_blocks)
{
    __shared__ int sh_off, sh_n;

    int tid = threadIdx.x;
    int s = blockIdx.y;
    int x = blockIdx.x;

    if (tid == 0) {
        int acc = 0;
        for (int k = 0; k < s; k++) acc += slice_mask[k];
        sh_off = acc;
        sh_n   = slice_mask[s];
    }
    __syncthreads();
    int off = sh_off, n = sh_n;
    int npre = n < 4 ? n : 4;

    if (x < bert_blocks) {
        // two j's per thread: j0 and j0 + half_bert
        int j0 = x * blockDim.x + tid;
        int j1 = j0 + half_bert;

        float4 v0[4], v1[4];
        #pragma unroll
        for (int k = 0; k < 4; k++) {
            if (k < npre) {
                size_t base = (size_t)(off + k) * vec_bert;
                v0[k] = bert[base + j0];
                v1[k] = bert[base + j1];
            }
        }

        cudaGridDependencySynchronize();

        float4 a0 = make_float4(0.f, 0.f, 0.f, 0.f);
        float4 a1 = make_float4(0.f, 0.f, 0.f, 0.f);
        #pragma unroll
        for (int k = 0; k < 4; k++) {
            if (k < npre) {
                float w = g_w[off + k];
                a0.x += w * v0[k].x; a0.y += w * v0[k].y;
                a0.z += w * v0[k].z; a0.w += w * v0[k].w;
                a1.x += w * v1[k].x; a1.y += w * v1[k].y;
                a1.z += w * v1[k].z; a1.w += w * v1[k].w;
            }
        }
        for (int k = 4; k < n; k++) {          // tail only if n > 4
            float w = g_w[off + k];
            size_t base = (size_t)(off + k) * vec_bert;
            float4 u0 = bert[base + j0];
            float4 u1 = bert[base + j1];
            a0.x += w * u0.x; a0.y += w * u0.y;
            a0.z += w * u0.z; a0.w += w * u0.w;
            a1.x += w * u1.x; a1.y += w * u1.y;
            a1.z += w * u1.z; a1.w += w * u1.w;
        }
        size_t ob = (size_t)s * vec_bert;
        out_bert[ob + j0] = a0;
        out_bert[ob + j1] = a1;
    } else {
        // mtl slot
        int j = tid;
        bool active = (j < vec_mtl);
        float4 v[4];
        #pragma unroll
        for (int k = 0; k < 4; k++)
            if (active && k < npre) v[k] = mtl[(size_t)(off + k) * vec_mtl + j];

        cudaGridDependencySynchronize();

        if (active) {
            float4 a = make_float4(0.f, 0.f, 0.f, 0.f);
            #pragma unroll
            for (int k = 0; k < 4; k++) {
                if (k < npre) {
                    float w = g_w[off + k];
                    a.x += w * v[k].x; a.y += w * v[k].y;
                    a.z += w * v[k].z; a.w += w * v[k].w;
                }
            }
            for (int k = 4; k < n; k++) {
                float w = g_w[off + k];
                float4 u = mtl[(size_t)(off + k) * vec_mtl + j];
                a.x += w * u.x; a.y += w * u.y;
                a.z += w * u.z; a.w += w * u.w;
            }
            out_mtl[(size_t)s * vec_mtl + j] = a;
        }
    }
}

extern "C" void kernel_launch(void* const* d_in, const int* in_sizes, int n_in,
                              void* d_out, int out_size)
{
    const float* bert       = (const float*)d_in[0];
    const float* hist       = (const float*)d_in[1];
    const float* mtl        = (const float*)d_in[2];
    const float* W          = (const float*)d_in[3];
    const float* b          = (const float*)d_in[4];
    const int*   slice_mask = (const int*)  d_in[5];

    int rows = in_sizes[1] / HIDDEN;                 // 64
    int seqh = in_sizes[0] / rows;                   // 512*768
    int per_s = seqh + HIDDEN + MAX_T;
    int S = out_size / per_s;                        // 16

    float* out        = (float*)d_out;
    float* out_bert   = out;
    float* out_mtl    = out_bert + (size_t)S * seqh;
    float* out_probs  = out_mtl  + (size_t)S * HIDDEN;

    int vec_bert  = seqh / 4;                        // 98304
    int half_bert = vec_bert / 2;                    // 49152
    int vec_mtl   = HIDDEN / 4;                      // 192
    int bert_blocks = half_bert / 256;               // 192

    // Primary (PDL trigger at entry)
    k_weights<<<S, 32 * MAX_T>>>(hist, W, b, slice_mask, out_probs, rows, S);

    // Secondary with programmatic dependent launch
    cudaLaunchConfig_t cfg = {};
    cfg.gridDim  = dim3(bert_blocks + 1, S);
    cfg.blockDim = dim3(256);
    cudaLaunchAttribute attr[1];
    attr[0].id = cudaLaunchAttributeProgrammaticStreamSerialization;
    attr[0].val.programmaticStreamSerializationAllowed = 1;
    cfg.attrs = attr;
    cfg.numAttrs = 1;

    cudaLaunchKernelEx(&cfg, k_segsum,
                       (const float4*)bert, (float4*)out_bert,
                       (const float4*)mtl, (float4*)out_mtl,
                       slice_mask, half_bert, vec_bert, vec_mtl, bert_blocks);
}

// round 15
// speedup vs baseline: 1.0748x; 1.0748x over previous
#include <cuda_runtime.h>
#include <cuda_bf16.h>
#include <math.h>

#define MAX_T 11
#define HIDDEN 768
#define MAX_S 64
#define MAX_ROWS 64

// Scratch (no device allocation allowed).
__device__ float g_w[MAX_ROWS];

// ---------------------------------------------------------------------------
// K1: single-stage weights producer. One block per slice; warp d computes the
// dot product for valid turn d (row off+d), block does the softmax locally.
// No inter-block communication -> latency = one DRAM round trip (~2us).
// ---------------------------------------------------------------------------
__global__ void __launch_bounds__(32 * MAX_T)
k_weights(const float* __restrict__ hist,
          const float* __restrict__ W,
          const float* __restrict__ b,
          const int*   __restrict__ slice_mask,
          float* __restrict__ out_probs,
          int rows, int S)
{
    cudaTriggerProgrammaticLaunchCompletion();

    __shared__ int   s_mask[MAX_S];
    __shared__ float s_e[MAX_T];

    int tid  = threadIdx.x;
    int warp = tid >> 5, lane = tid & 31;
    int s = blockIdx.x;

    if (tid < S) s_mask[tid] = slice_mask[tid];
    __syncthreads();

    int off = 0;
    #pragma unroll 4
    for (int k = 0; k < s; k++) off += s_mask[k];
    int n = s_mask[s];
    if (n > MAX_T) n = MAX_T;

    // warp d -> dot(hist[off+d], W); batch all loads first (MLP=6+6)
    if (warp < n) {
        int idx = off + warp;
        if (idx < 0) idx = 0;
        if (idx >= rows) idx = rows - 1;
        const float4* h4 = (const float4*)(hist + (size_t)idx * HIDDEN);
        const float4* w4 = (const float4*)W;
        float4 hv[6], wv[6];
        #pragma unroll
        for (int c = 0; c < 6; c++) hv[c] = h4[lane + c * 32];
        #pragma unroll
        for (int c = 0; c < 6; c++) wv[c] = w4[lane + c * 32];
        float acc = 0.f;
        #pragma unroll
        for (int c = 0; c < 6; c++)
            acc += hv[c].x * wv[c].x + hv[c].y * wv[c].y +
                   hv[c].z * wv[c].z + hv[c].w * wv[c].w;
        #pragma unroll
        for (int o = 16; o; o >>= 1) acc += __shfl_xor_sync(0xffffffffu, acc, o);
        if (lane == 0) s_e[warp] = __expf(acc + b[0]);
    }
    __syncthreads();

    float sum = 0.f;
    #pragma unroll 4
    for (int k = 0; k < n; k++) sum += s_e[k];
    float inv = 1.f / sum;

    int pad = MAX_T - n;
    if (tid < MAX_T)
        out_probs[s * MAX_T + tid] = (tid < pad) ? 0.f : s_e[tid - pad] * inv;
    if (tid < n)
        g_w[off + tid] = s_e[tid] * inv;
}

// ---------------------------------------------------------------------------
// K2: weighted segment sum (PDL secondary). One float4 output per thread,
// regs ~40 -> high occupancy (this exact shape measured 21.1us @ 65.9% DRAM).
// Preloads issued before the grid-dependency sync overlap K1 entirely.
// ---------------------------------------------------------------------------
__global__ void __launch_bounds__(256)
k_segsum(const float4* __restrict__ bert,
         float4* __restrict__ out_bert,
         const float4* __restrict__ mtl,
         float4* __restrict__ out_mtl,
         const int* __restrict__ slice_mask,
         int vec_bert, int vec_mtl, int bert_blocks)
{
    __shared__ int sh_off, sh_n;

    int tid = threadIdx.x;
    int s = blockIdx.y;
    int x = blockIdx.x;

    if (tid == 0) {
        int acc = 0;
        for (int k = 0; k < s; k++) acc += slice_mask[k];
        sh_off = acc;
        sh_n   = slice_mask[s];
    }
    __syncthreads();
    int off = sh_off, n = sh_n;

    const float4* in;
    float4* out;
    int vec, j;
    if (x < bert_blocks) {
        in = bert; out = out_bert; vec = vec_bert;
        j = x * blockDim.x + tid;
    } else {
        in = mtl; out = out_mtl; vec = vec_mtl;
        j = tid;
    }
    bool active = (j < vec);

    // Preload up to 4 rows before the dependency sync.
    float4 v[4];
    int npre = n < 4 ? n : 4;
    if (active) {
        #pragma unroll
        for (int k = 0; k < 4; k++)
            if (k < npre) v[k] = in[(size_t)(off + k) * vec + j];
    }

    cudaGridDependencySynchronize();   // HW wait for K1 grid completion

    if (active) {
        float4 acc = make_float4(0.f, 0.f, 0.f, 0.f);
        #pragma unroll
        for (int k = 0; k < 4; k++) {
            if (k < npre) {
                float w = g_w[off + k];
                acc.x += w * v[k].x; acc.y += w * v[k].y;
                acc.z += w * v[k].z; acc.w += w * v[k].w;
            }
        }
        for (int k = 4; k < n; k++) {          // tail only if n > 4
            float w = g_w[off + k];
            float4 u = in[(size_t)(off + k) * vec + j];
            acc.x += w * u.x; acc.y += w * u.y;
            acc.z += w * u.z; acc.w += w * u.w;
        }
        out[(size_t)s * vec + j] = acc;
    }
}

extern "C" void kernel_launch(void* const* d_in, const int* in_sizes, int n_in,
                              void* d_out, int out_size)
{
    const float* bert       = (const float*)d_in[0];
    const float* hist       = (const float*)d_in[1];
    const float* mtl        = (const float*)d_in[2];
    const float* W          = (const float*)d_in[3];
    const float* b          = (const float*)d_in[4];
    const int*   slice_mask = (const int*)  d_in[5];

    int rows = in_sizes[1] / HIDDEN;                 // 64
    int seqh = in_sizes[0] / rows;                   // 512*768
    int per_s = seqh + HIDDEN + MAX_T;
    int S = out_size / per_s;                        // 16

    float* out        = (float*)d_out;
    float* out_bert   = out;
    float* out_mtl    = out_bert + (size_t)S * seqh;
    float* out_probs  = out_mtl  + (size_t)S * HIDDEN;

    int vec_bert = seqh / 4;                         // 98304
    int vec_mtl  = HIDDEN / 4;                       // 192
    int bert_blocks = (vec_bert + 255) / 256;        // 384

    // Primary (PDL trigger at entry)
    k_weights<<<S, 32 * MAX_T>>>(hist, W, b, slice_mask, out_probs, rows, S);

    // Secondary with programmatic dependent launch
    cudaLaunchConfig_t cfg = {};
    cfg.gridDim  = dim3(bert_blocks + 1, S);
    cfg.blockDim = dim3(256);
    cudaLaunchAttribute attr[1];
    attr[0].id = cudaLaunchAttributeProgrammaticStreamSerialization;
    attr[0].val.programmaticStreamSerializationAllowed = 1;
    cfg.attrs = attr;
    cfg.numAttrs = 1;

    cudaLaunchKernelEx(&cfg, k_segsum,
                       (const float4*)bert, (float4*)out_bert,
                       (const float4*)mtl, (float4*)out_mtl,
                       slice_mask, vec_bert, vec_mtl, bert_blocks);
}